// round 15
// baseline (speedup 1.0000x reference)
#include <cuda_runtime.h>
#include <cuda_bf16.h>
#include <math.h>
#include <stdint.h>

#define B_    8
#define C_    384
#define HW_   4096
#define HWDIM 64
#define NG_   32
#define CPG_  12
#define KTOP_ 512
#define PI_F  3.14159265358979323846f

// ---------------- scratch (device globals; no allocation) ----------------
__device__ float g_xn [(size_t)B_ * C_ * HW_];
__device__ float g_q  [(size_t)B_ * C_ * HW_];
__device__ float g_k  [(size_t)B_ * C_ * HW_];
__device__ float g_v  [(size_t)B_ * C_ * HW_];
__device__ __nv_bfloat16 g_xnh[(size_t)B_ * C_ * HW_];
__device__ __nv_bfloat16 g_xnl[(size_t)B_ * C_ * HW_];
__device__ __nv_bfloat16 g_f4h[(size_t)B_ * C_ * HW_];
__device__ __nv_bfloat16 g_f4l[(size_t)B_ * C_ * HW_];
__device__ __nv_bfloat16 g_wkh[(size_t)384 * 3456];
__device__ __nv_bfloat16 g_wkl[(size_t)384 * 3456];
__device__ __nv_bfloat16 g_wqvh[(size_t)768 * 384], g_wqvl[(size_t)768 * 384];
__device__ __nv_bfloat16 g_wfh[384 * 384], g_wfl[384 * 384];
__device__ float g_bqv[768];

// ---------------- helpers ----------------
__device__ __forceinline__ void cp16(void* dst, const void* src) {
    unsigned d = (unsigned)__cvta_generic_to_shared(dst);
    asm volatile("cp.async.cg.shared.global [%0], [%1], 16;" :: "r"(d), "l"(src));
}
#define CP_COMMIT() asm volatile("cp.async.commit_group;" ::: "memory")
#define CP_WAIT0()  asm volatile("cp.async.wait_group 0;" ::: "memory")

__device__ __forceinline__ void ldm_x4(uint32_t* r, uint32_t addr) {
    asm volatile("ldmatrix.sync.aligned.m8n8.x4.shared.b16 {%0,%1,%2,%3}, [%4];"
        : "=r"(r[0]), "=r"(r[1]), "=r"(r[2]), "=r"(r[3]) : "r"(addr));
}
__device__ __forceinline__ void ldm_x4t(uint32_t* r, uint32_t addr) {
    asm volatile("ldmatrix.sync.aligned.m8n8.x4.trans.shared.b16 {%0,%1,%2,%3}, [%4];"
        : "=r"(r[0]), "=r"(r[1]), "=r"(r[2]), "=r"(r[3]) : "r"(addr));
}
__device__ __forceinline__ void mma_bf16(float* c, const uint32_t* a, const uint32_t* b) {
    asm volatile(
        "mma.sync.aligned.m16n8k16.row.col.f32.bf16.bf16.f32 "
        "{%0,%1,%2,%3}, {%4,%5,%6,%7}, {%8,%9}, {%0,%1,%2,%3};"
        : "+f"(c[0]), "+f"(c[1]), "+f"(c[2]), "+f"(c[3])
        : "r"(a[0]), "r"(a[1]), "r"(a[2]), "r"(a[3]), "r"(b[0]), "r"(b[1]));
}

// ---------------- merged prep ----------------
__device__ __forceinline__ void wsplit_body(
    const float* __restrict__ w, __nv_bfloat16* __restrict__ ht,
    __nv_bfloat16* __restrict__ lt, int K, int mrows, int moff, int blk)
{
    int idx = blk * 256 + threadIdx.x;
    int m  = idx % 384;
    int kt = idx / 384;
    if (kt >= (K >> 4)) return;
    const float4* src = (const float4*)(w + (size_t)m * K + kt * 16);
    uint4 ho[2], lo[2];
    uint32_t* hw = (uint32_t*)ho;
    uint32_t* lw = (uint32_t*)lo;
#pragma unroll
    for (int j = 0; j < 4; j++) {
        float4 v = src[j];
        __nv_bfloat162 h0 = __floats2bfloat162_rn(v.x, v.y);
        __nv_bfloat162 h1 = __floats2bfloat162_rn(v.z, v.w);
        __nv_bfloat162 l0 = __floats2bfloat162_rn(v.x - __bfloat162float(h0.x),
                                                  v.y - __bfloat162float(h0.y));
        __nv_bfloat162 l1 = __floats2bfloat162_rn(v.z - __bfloat162float(h1.x),
                                                  v.w - __bfloat162float(h1.y));
        hw[2 * j]     = *(uint32_t*)&h0;
        hw[2 * j + 1] = *(uint32_t*)&h1;
        lw[2 * j]     = *(uint32_t*)&l0;
        lw[2 * j + 1] = *(uint32_t*)&l1;
    }
    uint4* dh = (uint4*)(ht + ((size_t)kt * mrows + moff + m) * 16);
    uint4* dl = (uint4*)(lt + ((size_t)kt * mrows + moff + m) * 16);
    dh[0] = ho[0]; dh[1] = ho[1];
    dl[0] = lo[0]; dl[1] = lo[1];
}

__global__ void prep_kernel(const float* __restrict__ wq, const float* __restrict__ wv,
                            const float* __restrict__ wf, const float* __restrict__ wk,
                            const float* __restrict__ bq, const float* __restrict__ bv)
{
    int bx = blockIdx.x;
    if (bx < 36) {
        wsplit_body(wq, g_wqvh, g_wqvl, 384, 768, 0, bx);
    } else if (bx < 72) {
        wsplit_body(wv, g_wqvh, g_wqvl, 384, 768, 384, bx - 36);
    } else if (bx < 108) {
        wsplit_body(wf, g_wfh, g_wfl, 384, 384, 0, bx - 72);
    } else if (bx < 432) {
        wsplit_body(wk, g_wkh, g_wkl, 3456, 384, 0, bx - 108);
    } else {
        int i = threadIdx.x;
        for (; i < 768; i += 256)
            g_bqv[i] = (i < 384) ? bq[i] : bv[i - 384];
    }
}

// ---------------- GroupNorm ----------------
__global__ __launch_bounds__(256) void groupnorm_kernel(
    const float* __restrict__ x, const float* __restrict__ gamma,
    const float* __restrict__ beta)
{
    int b = blockIdx.x / NG_;
    int g = blockIdx.x % NG_;
    size_t base = ((size_t)b * C_ + (size_t)g * CPG_) * HW_;
    const int n = CPG_ * HW_;
    int tid = threadIdx.x;

    float s = 0.f, ss = 0.f;
    for (int i = tid * 4; i < n; i += 1024) {
        float4 v = *(const float4*)&x[base + i];
        s  += v.x + v.y + v.z + v.w;
        ss += v.x * v.x + v.y * v.y + v.z * v.z + v.w * v.w;
    }
    __shared__ float rs[256], rss[256];
    rs[tid] = s; rss[tid] = ss;
    __syncthreads();
    for (int o = 128; o > 0; o >>= 1) {
        if (tid < o) { rs[tid] += rs[tid + o]; rss[tid] += rss[tid + o]; }
        __syncthreads();
    }
    float mean = rs[0] / (float)n;
    float var  = rss[0] / (float)n - mean * mean;
    float inv  = rsqrtf(var + 1e-5f);

    for (int i = tid * 4; i < n; i += 1024) {
        int c = g * CPG_ + i / HW_;
        float ga = gamma[c], be = beta[c];
        float4 v = *(const float4*)&x[base + i];
        v.x = (v.x - mean) * inv * ga + be;
        v.y = (v.y - mean) * inv * ga + be;
        v.z = (v.z - mean) * inv * ga + be;
        v.w = (v.w - mean) * inv * ga + be;
        *(float4*)&g_xn[base + i] = v;
        __nv_bfloat162 h0 = __floats2bfloat162_rn(v.x, v.y);
        __nv_bfloat162 h1 = __floats2bfloat162_rn(v.z, v.w);
        __nv_bfloat162 l0 = __floats2bfloat162_rn(v.x - __bfloat162float(h0.x),
                                                  v.y - __bfloat162float(h0.y));
        __nv_bfloat162 l1 = __floats2bfloat162_rn(v.z - __bfloat162float(h1.x),
                                                  v.w - __bfloat162float(h1.y));
        *(__nv_bfloat162*)&g_xnh[base + i]     = h0;
        *(__nv_bfloat162*)&g_xnh[base + i + 2] = h1;
        *(__nv_bfloat162*)&g_xnl[base + i]     = l0;
        *(__nv_bfloat162*)&g_xnl[base + i + 2] = l1;
    }
}

// ---------------- bf16 split tensor-core GEMM (BK=16, x4t B fragments) ----------------
#define AH_O(p) ((p) * 4096)
#define AL_O(p) (8192 + (p) * 4096)
#define BH_O(p) (16384 + (p) * 4096)
#define BL_O(p) (24576 + (p) * 4096)

template <int KTOT, int MROWS, bool CONV3, bool MULXN>
__global__ __launch_bounds__(256) void gemm_bf16_kernel(
    const __nv_bfloat16* __restrict__ whT, const __nv_bfloat16* __restrict__ wlT,
    const __nv_bfloat16* __restrict__ bhp, const __nv_bfloat16* __restrict__ blp,
    const float* __restrict__ xraw,
    const float* __restrict__ bias, float* __restrict__ Y0, float* __restrict__ Y1)
{
    __shared__ __align__(16) char smem[32768];
    const uint32_t sb = (uint32_t)__cvta_generic_to_shared(smem);

    const int b  = blockIdx.z;
    const int n0 = blockIdx.x * 128;
    const int m0 = blockIdx.y * 128;
    const __nv_bfloat16* BhG = bhp + (size_t)b * C_ * HW_;
    const __nv_bfloat16* BlG = blp + (size_t)b * C_ * HW_;
    const float* Xb = xraw + (size_t)b * C_ * HW_;

    const int tid  = threadIdx.x;
    const int lane = tid & 31;
    const int wid  = tid >> 5;
    const int wm   = wid & 1;
    const int wn   = wid >> 1;
    const int g    = lane >> 2;
    const int t    = lane & 3;

    const int am = tid >> 1, ac = tid & 1;
    const int bk = tid >> 4, bc = tid & 15;
    const uint32_t aPhys = (uint32_t)((((am * 2 + ac) ^ ((am >> 2) & 1))) * 16);
    const uint32_t bPhys = (uint32_t)(bk * 256 + (((bc & 8) | ((bc ^ bk) & 7))) * 16);

    const int ml = lane & 15, kcl = lane >> 4;
    uint32_t aOff[4];
#pragma unroll
    for (int mi = 0; mi < 4; mi++) {
        int m = wm * 64 + mi * 16 + ml;
        aOff[mi] = (uint32_t)((((m * 2 + kcl) ^ ((m >> 2) & 1))) * 16);
    }
    uint32_t bOff4[2];
    {
        const int kl = lane & 15;
        const int ch = lane >> 4;
#pragma unroll
        for (int p4 = 0; p4 < 2; p4++) {
            int c = wn * 4 + p4 * 2 + ch;
            int cc = (c & 8) | ((c ^ (kl & 7)) & 7);
            bOff4[p4] = (uint32_t)(kl * 256 + cc * 16);
        }
    }

    // conv3x3 gather state
    const int wb    = (bc * 8) & 63;
    const int hbase = (n0 + bc * 8) >> 6;
    int ci = bk / 9;
    int rs = bk - ci * 9;

    float acc[4][4][4];
#pragma unroll
    for (int mi = 0; mi < 4; mi++)
#pragma unroll
        for (int ni = 0; ni < 4; ni++)
#pragma unroll
            for (int r = 0; r < 4; r++) acc[mi][ni][r] = 0.f;

    const int NIT = KTOT / 16;
    float cv[8];

    {
        const __nv_bfloat16* sh = whT + ((size_t)0 * MROWS + m0 + am) * 16 + ac * 8;
        const __nv_bfloat16* sl = wlT + ((size_t)0 * MROWS + m0 + am) * 16 + ac * 8;
        cp16(smem + AH_O(0) + aPhys, sh);
        cp16(smem + AL_O(0) + aPhys, sl);
        if (!CONV3) {
            cp16(smem + BH_O(0) + bPhys, BhG + (size_t)bk * HW_ + n0 + bc * 8);
            cp16(smem + BL_O(0) + bPhys, BlG + (size_t)bk * HW_ + n0 + bc * 8);
        }
        CP_COMMIT();
        if (CONV3) {
            const int dyq = (rs * 11) >> 5;
            const int dy = dyq - 1, dx = rs - dyq * 3 - 1;
            const int hh = hbase + dy;
            const bool hok = (hh >= 0 && hh < HWDIM);
            const float* xrow = Xb + (size_t)ci * HW_ + hh * HWDIM + wb + dx;
            if (hok) {
                cv[0] = (wb + dx < 0) ? 0.f : xrow[0];
#pragma unroll
                for (int j = 1; j < 7; j++) cv[j] = xrow[j];
                cv[7] = (wb + dx > 56) ? 0.f : xrow[7];
            } else {
#pragma unroll
                for (int j = 0; j < 8; j++) cv[j] = 0.f;
            }
            uint32_t ph[4], pl[4];
#pragma unroll
            for (int jj = 0; jj < 4; jj++) {
                __nv_bfloat162 h2 = __floats2bfloat162_rn(cv[2 * jj], cv[2 * jj + 1]);
                float la = cv[2 * jj]     - __bfloat162float(h2.x);
                float lb = cv[2 * jj + 1] - __bfloat162float(h2.y);
                __nv_bfloat162 l2 = __floats2bfloat162_rn(la, lb);
                ph[jj] = *(uint32_t*)&h2;
                pl[jj] = *(uint32_t*)&l2;
            }
            *(uint4*)(smem + BH_O(0) + bPhys) = make_uint4(ph[0], ph[1], ph[2], ph[3]);
            *(uint4*)(smem + BL_O(0) + bPhys) = make_uint4(pl[0], pl[1], pl[2], pl[3]);
        }
    }

    for (int it = 0; it < NIT; it++) {
        const int p = it & 1;
        const int q = 1 - p;

        CP_WAIT0();
        __syncthreads();

        const bool next = (it + 1 < NIT);
        if (next) {
            const int kt = it + 1;
            const __nv_bfloat16* sh = whT + ((size_t)kt * MROWS + m0 + am) * 16 + ac * 8;
            const __nv_bfloat16* sl = wlT + ((size_t)kt * MROWS + m0 + am) * 16 + ac * 8;
            cp16(smem + AH_O(q) + aPhys, sh);
            cp16(smem + AL_O(q) + aPhys, sl);
            if (!CONV3) {
                const int k0 = kt * 16;
                cp16(smem + BH_O(q) + bPhys, BhG + (size_t)(k0 + bk) * HW_ + n0 + bc * 8);
                cp16(smem + BL_O(q) + bPhys, BlG + (size_t)(k0 + bk) * HW_ + n0 + bc * 8);
            }
            CP_COMMIT();
            if (CONV3) {
                rs += 7; ci += 1;
                if (rs >= 9) { rs -= 9; ci += 1; }
                const int dyq = (rs * 11) >> 5;
                const int dy = dyq - 1, dx = rs - dyq * 3 - 1;
                const int hh = hbase + dy;
                const bool hok = (hh >= 0 && hh < HWDIM);
                const float* xrow = Xb + (size_t)ci * HW_ + hh * HWDIM + wb + dx;
                if (hok) {
                    cv[0] = (wb + dx < 0) ? 0.f : xrow[0];
#pragma unroll
                    for (int j = 1; j < 7; j++) cv[j] = xrow[j];
                    cv[7] = (wb + dx > 56) ? 0.f : xrow[7];
                } else {
#pragma unroll
                    for (int j = 0; j < 8; j++) cv[j] = 0.f;
                }
            }
        }

        {
            const uint32_t aH = sb + AH_O(p), aL = sb + AL_O(p);
            const uint32_t bH = sb + BH_O(p), bL = sb + BL_O(p);

            uint32_t ah[4][4], al[4][4], bh[4][2], bx[4][2];
#pragma unroll
            for (int mi = 0; mi < 4; mi++) ldm_x4(ah[mi], aH + aOff[mi]);
#pragma unroll
            for (int p4 = 0; p4 < 2; p4++) {
                uint32_t r[4];
                ldm_x4t(r, bH + bOff4[p4]);
                bh[p4 * 2][0] = r[0]; bh[p4 * 2][1] = r[1];
                bh[p4 * 2 + 1][0] = r[2]; bh[p4 * 2 + 1][1] = r[3];
            }
#pragma unroll
            for (int mi = 0; mi < 4; mi++)
#pragma unroll
                for (int ni = 0; ni < 4; ni++) mma_bf16(acc[mi][ni], ah[mi], bh[ni]);
#pragma unroll
            for (int p4 = 0; p4 < 2; p4++) {
                uint32_t r[4];
                ldm_x4t(r, bL + bOff4[p4]);
                bx[p4 * 2][0] = r[0]; bx[p4 * 2][1] = r[1];
                bx[p4 * 2 + 1][0] = r[2]; bx[p4 * 2 + 1][1] = r[3];
            }
#pragma unroll
            for (int mi = 0; mi < 4; mi++)
#pragma unroll
                for (int ni = 0; ni < 4; ni++) mma_bf16(acc[mi][ni], ah[mi], bx[ni]);
#pragma unroll
            for (int mi = 0; mi < 4; mi++) ldm_x4(al[mi], aL + aOff[mi]);
#pragma unroll
            for (int mi = 0; mi < 4; mi++)
#pragma unroll
                for (int ni = 0; ni < 4; ni++) mma_bf16(acc[mi][ni], al[mi], bh[ni]);
        }

        if (next && CONV3) {
            uint32_t ph[4], pl[4];
#pragma unroll
            for (int jj = 0; jj < 4; jj++) {
                __nv_bfloat162 h2 = __floats2bfloat162_rn(cv[2 * jj], cv[2 * jj + 1]);
                float la = cv[2 * jj]     - __bfloat162float(h2.x);
                float lb = cv[2 * jj + 1] - __bfloat162float(h2.y);
                __nv_bfloat162 l2 = __floats2bfloat162_rn(la, lb);
                ph[jj] = *(uint32_t*)&h2;
                pl[jj] = *(uint32_t*)&l2;
            }
            *(uint4*)(smem + BH_O(q) + bPhys) = make_uint4(ph[0], ph[1], ph[2], ph[3]);
            *(uint4*)(smem + BL_O(q) + bPhys) = make_uint4(pl[0], pl[1], pl[2], pl[3]);
        }
        __syncthreads();
    }

    // ---- epilogue ----
    float* Yb = (MROWS > 384 && m0 >= 384) ? Y1 : Y0;
    const int mAdj = (MROWS > 384 && m0 >= 384) ? 384 : 0;
    const size_t ybase = (size_t)b * C_ * HW_;
#pragma unroll
    for (int mi = 0; mi < 4; mi++) {
        const int r0 = m0 + wm * 64 + mi * 16 + g;
        const int r1 = r0 + 8;
        const float bi0 = bias[r0];
        const float bi1 = bias[r1];
#pragma unroll
        for (int ni = 0; ni < 4; ni++) {
            const int col = n0 + wn * 32 + ni * 8 + 2 * t;
            float2 o0 = make_float2(acc[mi][ni][0] + bi0, acc[mi][ni][1] + bi0);
            float2 o1 = make_float2(acc[mi][ni][2] + bi1, acc[mi][ni][3] + bi1);
            size_t off0 = ybase + (size_t)(r0 - mAdj) * HW_ + col;
            size_t off1 = ybase + (size_t)(r1 - mAdj) * HW_ + col;
            if (MULXN) {
                float2 m0v = *(const float2*)&g_xn[off0];
                float2 m1v = *(const float2*)&g_xn[off1];
                o0.x *= m0v.x; o0.y *= m0v.y;
                o1.x *= m1v.x; o1.y *= m1v.y;
            }
            *(float2*)&Yb[off0] = o0;
            *(float2*)&Yb[off1] = o1;
        }
    }
}

// ---------------- fused packed FFT + top-k + softmax + v-mul (R13 tail) ----------------
#define FFT2_SMEM_BYTES (512 + 2 * 4096 * 8)   // 66048

__device__ __forceinline__ unsigned f2ord(float f) {
    unsigned b = __float_as_uint(f);
    return (b & 0x80000000u) ? ~b : (b | 0x80000000u);
}
__device__ __forceinline__ float ord2f(unsigned u) {
    unsigned b = (u & 0x80000000u) ? (u ^ 0x80000000u) : ~u;
    return __uint_as_float(b);
}

__global__ __launch_bounds__(512) void fft_topk_kernel(
    const float* __restrict__ Q, const float* __restrict__ Kk,
    const float* __restrict__ V,
    __nv_bfloat16* __restrict__ Hout, __nv_bfloat16* __restrict__ Lout)
{
    extern __shared__ float smf[];
    float2* tw = (float2*)smf;
    float2* Z  = (float2*)(smf + 128);
    float2* T  = Z + 4096;

    __shared__ unsigned hist[256];
    __shared__ unsigned red[512];
    __shared__ unsigned s_prefix;
    __shared__ int s_kk;
    __shared__ float s_maxf;

    int tid = threadIdx.x;
    size_t base = (size_t)blockIdx.x * HW_;
    int l  = tid & 63;
    int jb = (tid >> 6) * 8;

    if (tid < 64) {
        float ang = -2.f * PI_F * (float)tid / 64.f;
        tw[tid] = make_float2(cosf(ang), sinf(ang));
    }
    __syncthreads();

    for (int i = tid; i < 4096; i += 512)
        Z[i] = make_float2(Q[base + i], Kk[base + i]);
    __syncthreads();

    // forward stage A (columns)
    {
        float ar[8], ai[8];
#pragma unroll
        for (int jj = 0; jj < 8; jj++) { ar[jj] = 0.f; ai[jj] = 0.f; }
        for (int m = 0; m < 64; m++) {
            float2 z = Z[m * 64 + l];
#pragma unroll
            for (int jj = 0; jj < 8; jj++) {
                float2 c = tw[((jb + jj) * m) & 63];
                ar[jj] += c.x * z.x - c.y * z.y;
                ai[jj] += c.x * z.y + c.y * z.x;
            }
        }
#pragma unroll
        for (int jj = 0; jj < 8; jj++)
            T[(jb + jj) * 64 + l] = make_float2(ar[jj], ai[jj]);
    }
    __syncthreads();

    // forward stage B (rows)
    {
        float2 wl = tw[l];
        float cr = 1.f, ci = 0.f;
        float ar[8], ai[8];
#pragma unroll
        for (int jj = 0; jj < 8; jj++) { ar[jj] = 0.f; ai[jj] = 0.f; }
        for (int m = 0; m < 64; m++) {
#pragma unroll
            for (int jj = 0; jj < 8; jj++) {
                float2 t = T[(jb + jj) * 64 + m];
                ar[jj] += t.x * cr - t.y * ci;
                ai[jj] += t.x * ci + t.y * cr;
            }
            float nr = cr * wl.x - ci * wl.y;
            ci = cr * wl.y + ci * wl.x;
            cr = nr;
        }
#pragma unroll
        for (int jj = 0; jj < 8; jj++)
            Z[(jb + jj) * 64 + l] = make_float2(ar[jj], ai[jj]);
    }
    __syncthreads();

    // pointwise product: only columns u2 = 0..32 needed downstream
    for (int idx = tid; idx < 64 * 33; idx += 512) {
        int u1 = idx / 33, u2 = idx - u1 * 33;
        int n1 = (64 - u1) & 63, n2 = (64 - u2) & 63;
        float2 s = Z[u1 * 64 + u2], t2 = Z[n1 * 64 + n2];
        float s2x = s.x * s.x - s.y * s.y;
        float s2y = 2.f * s.x * s.y;
        float t2x = t2.x * t2.x - t2.y * t2.y;
        float t2y = 2.f * t2.x * t2.y;
        T[u1 * 64 + u2] = make_float2(s2y + t2y, -(s2x - t2x));
    }
    __syncthreads();

    // inverse stage A (columns 0..32 only)
    {
        const int lcol = tid & 31;
        const int jb4  = (tid >> 5) * 4;
        float ar[4], ai[4];
#pragma unroll
        for (int jj = 0; jj < 4; jj++) { ar[jj] = 0.f; ai[jj] = 0.f; }
        for (int m = 0; m < 64; m++) {
            float2 p = T[m * 64 + lcol];
#pragma unroll
            for (int jj = 0; jj < 4; jj++) {
                float2 c = tw[((jb4 + jj) * m) & 63];
                ar[jj] += c.x * p.x + c.y * p.y;
                ai[jj] += c.x * p.y - c.y * p.x;
            }
        }
#pragma unroll
        for (int jj = 0; jj < 4; jj++)
            Z[(jb4 + jj) * 64 + lcol] = make_float2(ar[jj], ai[jj]);
        if (tid < 64) {
            float a = 0.f, bimag = 0.f;
            for (int m = 0; m < 64; m++) {
                float2 p = T[m * 64 + 32];
                float2 c = tw[(tid * m) & 63];
                a     += c.x * p.x + c.y * p.y;
                bimag += c.x * p.y - c.y * p.x;
            }
            Z[tid * 64 + 32] = make_float2(a, bimag);
        }
    }
    __syncthreads();

    // inverse stage B (rows, Hermitian-folded)
    unsigned* ua = (unsigned*)T;
    {
        float2 wl = tw[l];
        float cr = wl.x, ci = wl.y;
        float ar[8];
#pragma unroll
        for (int jj = 0; jj < 8; jj++) ar[jj] = 0.f;
        for (int m = 1; m < 32; m++) {
#pragma unroll
            for (int jj = 0; jj < 8; jj++) {
                float2 t = Z[(jb + jj) * 64 + m];
                ar[jj] += t.x * cr + t.y * ci;
            }
            float nr = cr * wl.x - ci * wl.y;
            ci = cr * wl.y + ci * wl.x;
            cr = nr;
        }
        const float par = (l & 1) ? -1.f : 1.f;
        unsigned mymax = 0u;
#pragma unroll
        for (int jj = 0; jj < 8; jj++) {
            float z0  = Z[(jb + jj) * 64 + 0].x;
            float z32 = Z[(jb + jj) * 64 + 32].x;
            float a = (z0 + par * z32 + 2.f * ar[jj]) * (1.f / 16384.f);
            unsigned u = f2ord(a);
            ua[(jb + jj) * 64 + l] = u;
            mymax = max(mymax, u);
        }
        red[tid] = mymax;
    }
    __syncthreads();
    for (int o = 256; o > 0; o >>= 1) {
        if (tid < o) red[tid] = max(red[tid], red[tid + o]);
        __syncthreads();
    }
    if (tid == 0) {
        s_maxf = ord2f(red[0]);
        s_kk = KTOP_;
        s_prefix = 0u;
    }
    __syncthreads();

    for (int level = 3; level >= 0; level--) {
        if (tid < 256) hist[tid] = 0u;
        __syncthreads();
        int shift = level * 8;
        unsigned maskhi = (level == 3) ? 0u : (0xFFFFFFFFu << (shift + 8));
        unsigned prefix = s_prefix;
        for (int i = tid; i < 4096; i += 512) {
            unsigned u = ua[i];
            if ((u & maskhi) == prefix)
                atomicAdd(&hist[(u >> shift) & 255], 1u);
        }
        __syncthreads();
        if (tid == 0) {
            int kk = s_kk;
            unsigned cum = 0;
            int d = 255;
            for (; d >= 0; d--) {
                unsigned c = hist[d];
                if (cum + c >= (unsigned)kk) break;
                cum += c;
            }
            if (d < 0) d = 0;
            s_kk = kk - (int)cum;
            s_prefix = prefix | ((unsigned)d << shift);
        }
        __syncthreads();
    }

    unsigned thr = s_prefix;
    float maxf = s_maxf;

    float* redf = (float*)red;
    {
        float ssum = 0.f;
        for (int i = tid; i < 4096; i += 512) {
            unsigned u = ua[i];
            if (u >= thr) ssum += expf(ord2f(u) - maxf);
        }
        redf[tid] = ssum;
    }
    __syncthreads();
    for (int o = 256; o > 0; o >>= 1) {
        if (tid < o) redf[tid] += redf[tid + o];
        __syncthreads();
    }
    float inv = 1.f / redf[0];

    for (int i = tid * 2; i < 4096; i += 1024) {
        unsigned u0 = ua[i], u1 = ua[i + 1];
        float2 vv = *(const float2*)&V[base + i];
        float o0 = 0.f, o1 = 0.f;
        if (u0 >= thr) o0 = vv.x * expf(ord2f(u0) - maxf) * inv;
        if (u1 >= thr) o1 = vv.y * expf(ord2f(u1) - maxf) * inv;
        __nv_bfloat162 h2 = __floats2bfloat162_rn(o0, o1);
        __nv_bfloat162 l2 = __floats2bfloat162_rn(o0 - __bfloat162float(h2.x),
                                                  o1 - __bfloat162float(h2.y));
        *(__nv_bfloat162*)&Hout[base + i] = h2;
        *(__nv_bfloat162*)&Lout[base + i] = l2;
    }
}

// ---------------- launch ----------------
extern "C" void kernel_launch(void* const* d_in, const int* in_sizes, int n_in,
                              void* d_out, int out_size)
{
    const float* x     = (const float*)d_in[0];
    const float* gamma = (const float*)d_in[1];
    const float* beta  = (const float*)d_in[2];
    const float* wq    = (const float*)d_in[3];
    const float* bq    = (const float*)d_in[4];
    const float* wk    = (const float*)d_in[5];
    const float* bk    = (const float*)d_in[6];
    const float* wv    = (const float*)d_in[7];
    const float* bv    = (const float*)d_in[8];
    const float* wf    = (const float*)d_in[9];
    const float* bf    = (const float*)d_in[10];
    float* out = (float*)d_out;

    void *pxn, *pxnh, *pxnl, *pq, *pk, *pv, *pf4h, *pf4l;
    void *pwkh, *pwkl, *pwqvh, *pwqvl, *pwfh, *pwfl, *pbqv;
    cudaGetSymbolAddress(&pxn,  g_xn);
    cudaGetSymbolAddress(&pxnh, g_xnh);
    cudaGetSymbolAddress(&pxnl, g_xnl);
    cudaGetSymbolAddress(&pq,   g_q);
    cudaGetSymbolAddress(&pk,   g_k);
    cudaGetSymbolAddress(&pv,   g_v);
    cudaGetSymbolAddress(&pf4h, g_f4h);
    cudaGetSymbolAddress(&pf4l, g_f4l);
    cudaGetSymbolAddress(&pwkh, g_wkh);
    cudaGetSymbolAddress(&pwkl, g_wkl);
    cudaGetSymbolAddress(&pwqvh, g_wqvh);
    cudaGetSymbolAddress(&pwqvl, g_wqvl);
    cudaGetSymbolAddress(&pwfh, g_wfh);
    cudaGetSymbolAddress(&pwfl, g_wfl);
    cudaGetSymbolAddress(&pbqv, g_bqv);

    cudaFuncSetAttribute(fft_topk_kernel,
                         cudaFuncAttributeMaxDynamicSharedMemorySize, FFT2_SMEM_BYTES);

    // 0. merged prep
    prep_kernel<<<433, 256>>>(wq, wv, wf, wk, bq, bv);

    // 1. GroupNorm (+ bf16 hi/lo planes)
    groupnorm_kernel<<<B_ * NG_, 256>>>(x, gamma, beta);

    // 2. combined q|v projection (M=768, shared B operand)
    dim3 gqv(HW_ / 128, 768 / 128, B_);
    gemm_bf16_kernel<C_, 768, false, false><<<gqv, 256>>>(
        (const __nv_bfloat16*)pwqvh, (const __nv_bfloat16*)pwqvl,
        (const __nv_bfloat16*)pxnh, (const __nv_bfloat16*)pxnl,
        (const float*)pxn, (const float*)pbqv, (float*)pq, (float*)pv);

    // 3. k projection (3x3 implicit GEMM)
    dim3 gg(HW_ / 128, C_ / 128, B_);
    gemm_bf16_kernel<C_ * 9, 384, true, false><<<gg, 256>>>(
        (const __nv_bfloat16*)pwkh, (const __nv_bfloat16*)pwkl,
        (const __nv_bfloat16*)pxnh, (const __nv_bfloat16*)pxnl,
        (const float*)pxn, bk, (float*)pk, (float*)pk);

    // 4. fused packed FFT + top-k + softmax + v-mul -> bf16 F4 planes
    fft_topk_kernel<<<B_ * C_, 512, FFT2_SMEM_BYTES>>>(
        (const float*)pq, (const float*)pk, (const float*)pv,
        (__nv_bfloat16*)pf4h, (__nv_bfloat16*)pf4l);

    // 5. final 1x1 conv with xn-multiply epilogue
    gemm_bf16_kernel<C_, 384, false, true><<<gg, 256>>>(
        (const __nv_bfloat16*)pwfh, (const __nv_bfloat16*)pwfl,
        (const __nv_bfloat16*)pf4h, (const __nv_bfloat16*)pf4l,
        (const float*)pxn, bf, out, out);
}

// round 16
// speedup vs baseline: 1.0413x; 1.0413x over previous
#include <cuda_runtime.h>
#include <cuda_bf16.h>
#include <math.h>
#include <stdint.h>

#define B_    8
#define C_    384
#define HW_   4096
#define HWDIM 64
#define NG_   32
#define CPG_  12
#define KTOP_ 512
#define PI_F  3.14159265358979323846f

// ---------------- scratch (device globals; no allocation) ----------------
__device__ float g_xn [(size_t)B_ * C_ * HW_];
__device__ float g_q  [(size_t)B_ * C_ * HW_];
__device__ float g_k  [(size_t)B_ * C_ * HW_];
__device__ float g_v  [(size_t)B_ * C_ * HW_];
__device__ __nv_bfloat16 g_xnh[(size_t)B_ * C_ * HW_];
__device__ __nv_bfloat16 g_xnl[(size_t)B_ * C_ * HW_];
__device__ __nv_bfloat16 g_f4h[(size_t)B_ * C_ * HW_];
__device__ __nv_bfloat16 g_f4l[(size_t)B_ * C_ * HW_];
__device__ __nv_bfloat16 g_wkh[(size_t)384 * 3456];
__device__ __nv_bfloat16 g_wkl[(size_t)384 * 3456];
__device__ __nv_bfloat16 g_wqvh[(size_t)768 * 384], g_wqvl[(size_t)768 * 384];
__device__ __nv_bfloat16 g_wfh[384 * 384], g_wfl[384 * 384];
__device__ float g_bqv[768];

// ---------------- helpers ----------------
__device__ __forceinline__ void cp16(void* dst, const void* src) {
    unsigned d = (unsigned)__cvta_generic_to_shared(dst);
    asm volatile("cp.async.cg.shared.global [%0], [%1], 16;" :: "r"(d), "l"(src));
}
#define CP_COMMIT() asm volatile("cp.async.commit_group;" ::: "memory")
#define CP_WAIT0()  asm volatile("cp.async.wait_group 0;" ::: "memory")

__device__ __forceinline__ void ldm_x4(uint32_t* r, uint32_t addr) {
    asm volatile("ldmatrix.sync.aligned.m8n8.x4.shared.b16 {%0,%1,%2,%3}, [%4];"
        : "=r"(r[0]), "=r"(r[1]), "=r"(r[2]), "=r"(r[3]) : "r"(addr));
}
__device__ __forceinline__ void ldm_x2t(uint32_t* r, uint32_t addr) {
    asm volatile("ldmatrix.sync.aligned.m8n8.x2.trans.shared.b16 {%0,%1}, [%2];"
        : "=r"(r[0]), "=r"(r[1]) : "r"(addr));
}
__device__ __forceinline__ void ldm_x4t(uint32_t* r, uint32_t addr) {
    asm volatile("ldmatrix.sync.aligned.m8n8.x4.trans.shared.b16 {%0,%1,%2,%3}, [%4];"
        : "=r"(r[0]), "=r"(r[1]), "=r"(r[2]), "=r"(r[3]) : "r"(addr));
}
__device__ __forceinline__ void mma_bf16(float* c, const uint32_t* a, const uint32_t* b) {
    asm volatile(
        "mma.sync.aligned.m16n8k16.row.col.f32.bf16.bf16.f32 "
        "{%0,%1,%2,%3}, {%4,%5,%6,%7}, {%8,%9}, {%0,%1,%2,%3};"
        : "+f"(c[0]), "+f"(c[1]), "+f"(c[2]), "+f"(c[3])
        : "r"(a[0]), "r"(a[1]), "r"(a[2]), "r"(a[3]), "r"(b[0]), "r"(b[1]));
}

// ---------------- merged prep ----------------
__device__ __forceinline__ void wsplit_body(
    const float* __restrict__ w, __nv_bfloat16* __restrict__ ht,
    __nv_bfloat16* __restrict__ lt, int K, int mrows, int moff, int blk)
{
    int idx = blk * 256 + threadIdx.x;
    int m  = idx % 384;
    int kt = idx / 384;
    if (kt >= (K >> 4)) return;
    const float4* src = (const float4*)(w + (size_t)m * K + kt * 16);
    uint4 ho[2], lo[2];
    uint32_t* hw = (uint32_t*)ho;
    uint32_t* lw = (uint32_t*)lo;
#pragma unroll
    for (int j = 0; j < 4; j++) {
        float4 v = src[j];
        __nv_bfloat162 h0 = __floats2bfloat162_rn(v.x, v.y);
        __nv_bfloat162 h1 = __floats2bfloat162_rn(v.z, v.w);
        __nv_bfloat162 l0 = __floats2bfloat162_rn(v.x - __bfloat162float(h0.x),
                                                  v.y - __bfloat162float(h0.y));
        __nv_bfloat162 l1 = __floats2bfloat162_rn(v.z - __bfloat162float(h1.x),
                                                  v.w - __bfloat162float(h1.y));
        hw[2 * j]     = *(uint32_t*)&h0;
        hw[2 * j + 1] = *(uint32_t*)&h1;
        lw[2 * j]     = *(uint32_t*)&l0;
        lw[2 * j + 1] = *(uint32_t*)&l1;
    }
    uint4* dh = (uint4*)(ht + ((size_t)kt * mrows + moff + m) * 16);
    uint4* dl = (uint4*)(lt + ((size_t)kt * mrows + moff + m) * 16);
    dh[0] = ho[0]; dh[1] = ho[1];
    dl[0] = lo[0]; dl[1] = lo[1];
}

__global__ void prep_kernel(const float* __restrict__ wq, const float* __restrict__ wv,
                            const float* __restrict__ wf, const float* __restrict__ wk,
                            const float* __restrict__ bq, const float* __restrict__ bv)
{
    int bx = blockIdx.x;
    if (bx < 36) {
        wsplit_body(wq, g_wqvh, g_wqvl, 384, 768, 0, bx);
    } else if (bx < 72) {
        wsplit_body(wv, g_wqvh, g_wqvl, 384, 768, 384, bx - 36);
    } else if (bx < 108) {
        wsplit_body(wf, g_wfh, g_wfl, 384, 384, 0, bx - 72);
    } else if (bx < 432) {
        wsplit_body(wk, g_wkh, g_wkl, 3456, 384, 0, bx - 108);
    } else {
        int i = threadIdx.x;
        for (; i < 768; i += 256)
            g_bqv[i] = (i < 384) ? bq[i] : bv[i - 384];
    }
}

// ---------------- GroupNorm ----------------
__global__ __launch_bounds__(256) void groupnorm_kernel(
    const float* __restrict__ x, const float* __restrict__ gamma,
    const float* __restrict__ beta)
{
    int b = blockIdx.x / NG_;
    int g = blockIdx.x % NG_;
    size_t base = ((size_t)b * C_ + (size_t)g * CPG_) * HW_;
    const int n = CPG_ * HW_;
    int tid = threadIdx.x;

    float s = 0.f, ss = 0.f;
    for (int i = tid * 4; i < n; i += 1024) {
        float4 v = *(const float4*)&x[base + i];
        s  += v.x + v.y + v.z + v.w;
        ss += v.x * v.x + v.y * v.y + v.z * v.z + v.w * v.w;
    }
    __shared__ float rs[256], rss[256];
    rs[tid] = s; rss[tid] = ss;
    __syncthreads();
    for (int o = 128; o > 0; o >>= 1) {
        if (tid < o) { rs[tid] += rs[tid + o]; rss[tid] += rss[tid + o]; }
        __syncthreads();
    }
    float mean = rs[0] / (float)n;
    float var  = rss[0] / (float)n - mean * mean;
    float inv  = rsqrtf(var + 1e-5f);

    for (int i = tid * 4; i < n; i += 1024) {
        int c = g * CPG_ + i / HW_;
        float ga = gamma[c], be = beta[c];
        float4 v = *(const float4*)&x[base + i];
        v.x = (v.x - mean) * inv * ga + be;
        v.y = (v.y - mean) * inv * ga + be;
        v.z = (v.z - mean) * inv * ga + be;
        v.w = (v.w - mean) * inv * ga + be;
        *(float4*)&g_xn[base + i] = v;
        __nv_bfloat162 h0 = __floats2bfloat162_rn(v.x, v.y);
        __nv_bfloat162 h1 = __floats2bfloat162_rn(v.z, v.w);
        __nv_bfloat162 l0 = __floats2bfloat162_rn(v.x - __bfloat162float(h0.x),
                                                  v.y - __bfloat162float(h0.y));
        __nv_bfloat162 l1 = __floats2bfloat162_rn(v.z - __bfloat162float(h1.x),
                                                  v.w - __bfloat162float(h1.y));
        *(__nv_bfloat162*)&g_xnh[base + i]     = h0;
        *(__nv_bfloat162*)&g_xnh[base + i + 2] = h1;
        *(__nv_bfloat162*)&g_xnl[base + i]     = l0;
        *(__nv_bfloat162*)&g_xnl[base + i + 2] = l1;
    }
}

// ---------------- bf16 split tensor-core GEMM (BK=16; x4t B-frags only for CONV3) ----------------
#define AH_O(p) ((p) * 4096)
#define AL_O(p) (8192 + (p) * 4096)
#define BH_O(p) (16384 + (p) * 4096)
#define BL_O(p) (24576 + (p) * 4096)

template <int KTOT, int MROWS, bool CONV3, bool MULXN>
__global__ __launch_bounds__(256) void gemm_bf16_kernel(
    const __nv_bfloat16* __restrict__ whT, const __nv_bfloat16* __restrict__ wlT,
    const __nv_bfloat16* __restrict__ bhp, const __nv_bfloat16* __restrict__ blp,
    const float* __restrict__ xraw,
    const float* __restrict__ bias, float* __restrict__ Y0, float* __restrict__ Y1)
{
    __shared__ __align__(16) char smem[32768];
    const uint32_t sb = (uint32_t)__cvta_generic_to_shared(smem);

    const int b  = blockIdx.z;
    const int n0 = blockIdx.x * 128;
    const int m0 = blockIdx.y * 128;
    const __nv_bfloat16* BhG = bhp + (size_t)b * C_ * HW_;
    const __nv_bfloat16* BlG = blp + (size_t)b * C_ * HW_;
    const float* Xb = xraw + (size_t)b * C_ * HW_;

    const int tid  = threadIdx.x;
    const int lane = tid & 31;
    const int wid  = tid >> 5;
    const int wm   = wid & 1;
    const int wn   = wid >> 1;
    const int g    = lane >> 2;
    const int t    = lane & 3;

    const int am = tid >> 1, ac = tid & 1;
    const int bk = tid >> 4, bc = tid & 15;
    const uint32_t aPhys = (uint32_t)((((am * 2 + ac) ^ ((am >> 2) & 1))) * 16);
    const uint32_t bPhys = (uint32_t)(bk * 256 + (((bc & 8) | ((bc ^ bk) & 7))) * 16);

    const int ml = lane & 15, kcl = lane >> 4;
    uint32_t aOff[4];
#pragma unroll
    for (int mi = 0; mi < 4; mi++) {
        int m = wm * 64 + mi * 16 + ml;
        aOff[mi] = (uint32_t)((((m * 2 + kcl) ^ ((m >> 2) & 1))) * 16);
    }
    // x2t offsets (for 1x1 GEMMs)
    uint32_t bOff[4];
    {
        const int kl = lane & 15;
#pragma unroll
        for (int ni = 0; ni < 4; ni++) {
            int c = wn * 4 + ni;
            int cc = (c & 8) | ((c ^ (kl & 7)) & 7);
            bOff[ni] = (uint32_t)(kl * 256 + cc * 16);
        }
    }
    // x4t offsets (for conv3x3)
    uint32_t bOff4[2];
    {
        const int kl = lane & 15;
        const int ch = lane >> 4;
#pragma unroll
        for (int p4 = 0; p4 < 2; p4++) {
            int c = wn * 4 + p4 * 2 + ch;
            int cc = (c & 8) | ((c ^ (kl & 7)) & 7);
            bOff4[p4] = (uint32_t)(kl * 256 + cc * 16);
        }
    }

    // conv3x3 gather state
    const int wb    = (bc * 8) & 63;
    const int hbase = (n0 + bc * 8) >> 6;
    int ci = bk / 9;
    int rs = bk - ci * 9;

    float acc[4][4][4];
#pragma unroll
    for (int mi = 0; mi < 4; mi++)
#pragma unroll
        for (int ni = 0; ni < 4; ni++)
#pragma unroll
            for (int r = 0; r < 4; r++) acc[mi][ni][r] = 0.f;

    const int NIT = KTOT / 16;
    float cv[8];

    {
        const __nv_bfloat16* sh = whT + ((size_t)0 * MROWS + m0 + am) * 16 + ac * 8;
        const __nv_bfloat16* sl = wlT + ((size_t)0 * MROWS + m0 + am) * 16 + ac * 8;
        cp16(smem + AH_O(0) + aPhys, sh);
        cp16(smem + AL_O(0) + aPhys, sl);
        if (!CONV3) {
            cp16(smem + BH_O(0) + bPhys, BhG + (size_t)bk * HW_ + n0 + bc * 8);
            cp16(smem + BL_O(0) + bPhys, BlG + (size_t)bk * HW_ + n0 + bc * 8);
        }
        CP_COMMIT();
        if (CONV3) {
            const int dyq = (rs * 11) >> 5;
            const int dy = dyq - 1, dx = rs - dyq * 3 - 1;
            const int hh = hbase + dy;
            const bool hok = (hh >= 0 && hh < HWDIM);
            const float* xrow = Xb + (size_t)ci * HW_ + hh * HWDIM + wb + dx;
            if (hok) {
                cv[0] = (wb + dx < 0) ? 0.f : xrow[0];
#pragma unroll
                for (int j = 1; j < 7; j++) cv[j] = xrow[j];
                cv[7] = (wb + dx > 56) ? 0.f : xrow[7];
            } else {
#pragma unroll
                for (int j = 0; j < 8; j++) cv[j] = 0.f;
            }
            uint32_t ph[4], pl[4];
#pragma unroll
            for (int jj = 0; jj < 4; jj++) {
                __nv_bfloat162 h2 = __floats2bfloat162_rn(cv[2 * jj], cv[2 * jj + 1]);
                float la = cv[2 * jj]     - __bfloat162float(h2.x);
                float lb = cv[2 * jj + 1] - __bfloat162float(h2.y);
                __nv_bfloat162 l2 = __floats2bfloat162_rn(la, lb);
                ph[jj] = *(uint32_t*)&h2;
                pl[jj] = *(uint32_t*)&l2;
            }
            *(uint4*)(smem + BH_O(0) + bPhys) = make_uint4(ph[0], ph[1], ph[2], ph[3]);
            *(uint4*)(smem + BL_O(0) + bPhys) = make_uint4(pl[0], pl[1], pl[2], pl[3]);
        }
    }

    for (int it = 0; it < NIT; it++) {
        const int p = it & 1;
        const int q = 1 - p;

        CP_WAIT0();
        __syncthreads();

        const bool next = (it + 1 < NIT);
        if (next) {
            const int kt = it + 1;
            const __nv_bfloat16* sh = whT + ((size_t)kt * MROWS + m0 + am) * 16 + ac * 8;
            const __nv_bfloat16* sl = wlT + ((size_t)kt * MROWS + m0 + am) * 16 + ac * 8;
            cp16(smem + AH_O(q) + aPhys, sh);
            cp16(smem + AL_O(q) + aPhys, sl);
            if (!CONV3) {
                const int k0 = kt * 16;
                cp16(smem + BH_O(q) + bPhys, BhG + (size_t)(k0 + bk) * HW_ + n0 + bc * 8);
                cp16(smem + BL_O(q) + bPhys, BlG + (size_t)(k0 + bk) * HW_ + n0 + bc * 8);
            }
            CP_COMMIT();
            if (CONV3) {
                rs += 7; ci += 1;
                if (rs >= 9) { rs -= 9; ci += 1; }
                const int dyq = (rs * 11) >> 5;
                const int dy = dyq - 1, dx = rs - dyq * 3 - 1;
                const int hh = hbase + dy;
                const bool hok = (hh >= 0 && hh < HWDIM);
                const float* xrow = Xb + (size_t)ci * HW_ + hh * HWDIM + wb + dx;
                if (hok) {
                    cv[0] = (wb + dx < 0) ? 0.f : xrow[0];
#pragma unroll
                    for (int j = 1; j < 7; j++) cv[j] = xrow[j];
                    cv[7] = (wb + dx > 56) ? 0.f : xrow[7];
                } else {
#pragma unroll
                    for (int j = 0; j < 8; j++) cv[j] = 0.f;
                }
            }
        }

        {
            const uint32_t aH = sb + AH_O(p), aL = sb + AL_O(p);
            const uint32_t bH = sb + BH_O(p), bL = sb + BL_O(p);

            uint32_t ah[4][4], al[4][4], bh[4][2], bx[4][2];
#pragma unroll
            for (int mi = 0; mi < 4; mi++) ldm_x4(ah[mi], aH + aOff[mi]);
            if (CONV3) {
#pragma unroll
                for (int p4 = 0; p4 < 2; p4++) {
                    uint32_t r[4];
                    ldm_x4t(r, bH + bOff4[p4]);
                    bh[p4 * 2][0] = r[0]; bh[p4 * 2][1] = r[1];
                    bh[p4 * 2 + 1][0] = r[2]; bh[p4 * 2 + 1][1] = r[3];
                }
            } else {
#pragma unroll
                for (int ni = 0; ni < 4; ni++) ldm_x2t(bh[ni], bH + bOff[ni]);
            }
#pragma unroll
            for (int mi = 0; mi < 4; mi++)
#pragma unroll
                for (int ni = 0; ni < 4; ni++) mma_bf16(acc[mi][ni], ah[mi], bh[ni]);
            if (CONV3) {
#pragma unroll
                for (int p4 = 0; p4 < 2; p4++) {
                    uint32_t r[4];
                    ldm_x4t(r, bL + bOff4[p4]);
                    bx[p4 * 2][0] = r[0]; bx[p4 * 2][1] = r[1];
                    bx[p4 * 2 + 1][0] = r[2]; bx[p4 * 2 + 1][1] = r[3];
                }
            } else {
#pragma unroll
                for (int ni = 0; ni < 4; ni++) ldm_x2t(bx[ni], bL + bOff[ni]);
            }
#pragma unroll
            for (int mi = 0; mi < 4; mi++)
#pragma unroll
                for (int ni = 0; ni < 4; ni++) mma_bf16(acc[mi][ni], ah[mi], bx[ni]);
#pragma unroll
            for (int mi = 0; mi < 4; mi++) ldm_x4(al[mi], aL + aOff[mi]);
#pragma unroll
            for (int mi = 0; mi < 4; mi++)
#pragma unroll
                for (int ni = 0; ni < 4; ni++) mma_bf16(acc[mi][ni], al[mi], bh[ni]);
        }

        if (next && CONV3) {
            uint32_t ph[4], pl[4];
#pragma unroll
            for (int jj = 0; jj < 4; jj++) {
                __nv_bfloat162 h2 = __floats2bfloat162_rn(cv[2 * jj], cv[2 * jj + 1]);
                float la = cv[2 * jj]     - __bfloat162float(h2.x);
                float lb = cv[2 * jj + 1] - __bfloat162float(h2.y);
                __nv_bfloat162 l2 = __floats2bfloat162_rn(la, lb);
                ph[jj] = *(uint32_t*)&h2;
                pl[jj] = *(uint32_t*)&l2;
            }
            *(uint4*)(smem + BH_O(q) + bPhys) = make_uint4(ph[0], ph[1], ph[2], ph[3]);
            *(uint4*)(smem + BL_O(q) + bPhys) = make_uint4(pl[0], pl[1], pl[2], pl[3]);
        }
        __syncthreads();
    }

    // ---- epilogue ----
    float* Yb = (MROWS > 384 && m0 >= 384) ? Y1 : Y0;
    const int mAdj = (MROWS > 384 && m0 >= 384) ? 384 : 0;
    const size_t ybase = (size_t)b * C_ * HW_;
#pragma unroll
    for (int mi = 0; mi < 4; mi++) {
        const int r0 = m0 + wm * 64 + mi * 16 + g;
        const int r1 = r0 + 8;
        const float bi0 = bias[r0];
        const float bi1 = bias[r1];
#pragma unroll
        for (int ni = 0; ni < 4; ni++) {
            const int col = n0 + wn * 32 + ni * 8 + 2 * t;
            float2 o0 = make_float2(acc[mi][ni][0] + bi0, acc[mi][ni][1] + bi0);
            float2 o1 = make_float2(acc[mi][ni][2] + bi1, acc[mi][ni][3] + bi1);
            size_t off0 = ybase + (size_t)(r0 - mAdj) * HW_ + col;
            size_t off1 = ybase + (size_t)(r1 - mAdj) * HW_ + col;
            if (MULXN) {
                float2 m0v = *(const float2*)&g_xn[off0];
                float2 m1v = *(const float2*)&g_xn[off1];
                o0.x *= m0v.x; o0.y *= m0v.y;
                o1.x *= m1v.x; o1.y *= m1v.y;
            }
            *(float2*)&Yb[off0] = o0;
            *(float2*)&Yb[off1] = o1;
        }
    }
}

// ---------------- fused packed FFT + top-k + softmax + v-mul (R13 version) ----------------
#define FFT2_SMEM_BYTES (512 + 2 * 4096 * 8)   // 66048

__device__ __forceinline__ unsigned f2ord(float f) {
    unsigned b = __float_as_uint(f);
    return (b & 0x80000000u) ? ~b : (b | 0x80000000u);
}
__device__ __forceinline__ float ord2f(unsigned u) {
    unsigned b = (u & 0x80000000u) ? (u ^ 0x80000000u) : ~u;
    return __uint_as_float(b);
}

__global__ __launch_bounds__(512) void fft_topk_kernel(
    const float* __restrict__ Q, const float* __restrict__ Kk,
    const float* __restrict__ V,
    __nv_bfloat16* __restrict__ Hout, __nv_bfloat16* __restrict__ Lout)
{
    extern __shared__ float smf[];
    float2* tw = (float2*)smf;
    float2* Z  = (float2*)(smf + 128);
    float2* T  = Z + 4096;

    __shared__ unsigned hist[256];
    __shared__ unsigned red[512];
    __shared__ unsigned s_prefix;
    __shared__ int s_kk;
    __shared__ float s_maxf;

    int tid = threadIdx.x;
    size_t base = (size_t)blockIdx.x * HW_;
    int l  = tid & 63;
    int jb = (tid >> 6) * 8;

    if (tid < 64) {
        float ang = -2.f * PI_F * (float)tid / 64.f;
        tw[tid] = make_float2(cosf(ang), sinf(ang));
    }
    __syncthreads();

    for (int i = tid; i < 4096; i += 512)
        Z[i] = make_float2(Q[base + i], Kk[base + i]);
    __syncthreads();

    // forward stage A (columns)
    {
        float ar[8], ai[8];
#pragma unroll
        for (int jj = 0; jj < 8; jj++) { ar[jj] = 0.f; ai[jj] = 0.f; }
        for (int m = 0; m < 64; m++) {
            float2 z = Z[m * 64 + l];
#pragma unroll
            for (int jj = 0; jj < 8; jj++) {
                float2 c = tw[((jb + jj) * m) & 63];
                ar[jj] += c.x * z.x - c.y * z.y;
                ai[jj] += c.x * z.y + c.y * z.x;
            }
        }
#pragma unroll
        for (int jj = 0; jj < 8; jj++)
            T[(jb + jj) * 64 + l] = make_float2(ar[jj], ai[jj]);
    }
    __syncthreads();

    // forward stage B (rows)
    {
        float2 wl = tw[l];
        float cr = 1.f, ci = 0.f;
        float ar[8], ai[8];
#pragma unroll
        for (int jj = 0; jj < 8; jj++) { ar[jj] = 0.f; ai[jj] = 0.f; }
        for (int m = 0; m < 64; m++) {
#pragma unroll
            for (int jj = 0; jj < 8; jj++) {
                float2 t = T[(jb + jj) * 64 + m];
                ar[jj] += t.x * cr - t.y * ci;
                ai[jj] += t.x * ci + t.y * cr;
            }
            float nr = cr * wl.x - ci * wl.y;
            ci = cr * wl.y + ci * wl.x;
            cr = nr;
        }
#pragma unroll
        for (int jj = 0; jj < 8; jj++)
            Z[(jb + jj) * 64 + l] = make_float2(ar[jj], ai[jj]);
    }
    __syncthreads();

    // pointwise product: only columns u2 = 0..32 needed downstream
    for (int idx = tid; idx < 64 * 33; idx += 512) {
        int u1 = idx / 33, u2 = idx - u1 * 33;
        int n1 = (64 - u1) & 63, n2 = (64 - u2) & 63;
        float2 s = Z[u1 * 64 + u2], t2 = Z[n1 * 64 + n2];
        float s2x = s.x * s.x - s.y * s.y;
        float s2y = 2.f * s.x * s.y;
        float t2x = t2.x * t2.x - t2.y * t2.y;
        float t2y = 2.f * t2.x * t2.y;
        T[u1 * 64 + u2] = make_float2(s2y + t2y, -(s2x - t2x));
    }
    __syncthreads();

    // inverse stage A (columns 0..32 only)
    {
        const int lcol = tid & 31;
        const int jb4  = (tid >> 5) * 4;
        float ar[4], ai[4];
#pragma unroll
        for (int jj = 0; jj < 4; jj++) { ar[jj] = 0.f; ai[jj] = 0.f; }
        for (int m = 0; m < 64; m++) {
            float2 p = T[m * 64 + lcol];
#pragma unroll
            for (int jj = 0; jj < 4; jj++) {
                float2 c = tw[((jb4 + jj) * m) & 63];
                ar[jj] += c.x * p.x + c.y * p.y;
                ai[jj] += c.x * p.y - c.y * p.x;
            }
        }
#pragma unroll
        for (int jj = 0; jj < 4; jj++)
            Z[(jb4 + jj) * 64 + lcol] = make_float2(ar[jj], ai[jj]);
        if (tid < 64) {
            float a = 0.f, bimag = 0.f;
            for (int m = 0; m < 64; m++) {
                float2 p = T[m * 64 + 32];
                float2 c = tw[(tid * m) & 63];
                a     += c.x * p.x + c.y * p.y;
                bimag += c.x * p.y - c.y * p.x;
            }
            Z[tid * 64 + 32] = make_float2(a, bimag);
        }
    }
    __syncthreads();

    // inverse stage B (rows, Hermitian-folded)
    unsigned* ua = (unsigned*)T;
    {
        float2 wl = tw[l];
        float cr = wl.x, ci = wl.y;
        float ar[8];
#pragma unroll
        for (int jj = 0; jj < 8; jj++) ar[jj] = 0.f;
        for (int m = 1; m < 32; m++) {
#pragma unroll
            for (int jj = 0; jj < 8; jj++) {
                float2 t = Z[(jb + jj) * 64 + m];
                ar[jj] += t.x * cr + t.y * ci;
            }
            float nr = cr * wl.x - ci * wl.y;
            ci = cr * wl.y + ci * wl.x;
            cr = nr;
        }
        const float par = (l & 1) ? -1.f : 1.f;
        unsigned mymax = 0u;
#pragma unroll
        for (int jj = 0; jj < 8; jj++) {
            float z0  = Z[(jb + jj) * 64 + 0].x;
            float z32 = Z[(jb + jj) * 64 + 32].x;
            float a = (z0 + par * z32 + 2.f * ar[jj]) * (1.f / 16384.f);
            unsigned u = f2ord(a);
            ua[(jb + jj) * 64 + l] = u;
            mymax = max(mymax, u);
        }
        red[tid] = mymax;
    }
    __syncthreads();
    for (int o = 256; o > 0; o >>= 1) {
        if (tid < o) red[tid] = max(red[tid], red[tid + o]);
        __syncthreads();
    }
    if (tid == 0) {
        s_maxf = ord2f(red[0]);
        s_kk = KTOP_;
        s_prefix = 0u;
    }
    __syncthreads();

    for (int level = 3; level >= 0; level--) {
        if (tid < 256) hist[tid] = 0u;
        __syncthreads();
        int shift = level * 8;
        unsigned maskhi = (level == 3) ? 0u : (0xFFFFFFFFu << (shift + 8));
        unsigned prefix = s_prefix;
        for (int i = tid; i < 4096; i += 512) {
            unsigned u = ua[i];
            if ((u & maskhi) == prefix)
                atomicAdd(&hist[(u >> shift) & 255], 1u);
        }
        __syncthreads();
        if (tid == 0) {
            int kk = s_kk;
            unsigned cum = 0;
            int d = 255;
            for (; d >= 0; d--) {
                unsigned c = hist[d];
                if (cum + c >= (unsigned)kk) break;
                cum += c;
            }
            if (d < 0) d = 0;
            s_kk = kk - (int)cum;
            s_prefix = prefix | ((unsigned)d << shift);
        }
        __syncthreads();
    }

    unsigned thr = s_prefix;
    float maxf = s_maxf;

    float* redf = (float*)red;
    {
        float ssum = 0.f;
        for (int i = tid; i < 4096; i += 512) {
            unsigned u = ua[i];
            if (u >= thr) ssum += expf(ord2f(u) - maxf);
        }
        redf[tid] = ssum;
    }
    __syncthreads();
    for (int o = 256; o > 0; o >>= 1) {
        if (tid < o) redf[tid] += redf[tid + o];
        __syncthreads();
    }
    float inv = 1.f / redf[0];

    for (int i = tid * 2; i < 4096; i += 1024) {
        unsigned u0 = ua[i], u1 = ua[i + 1];
        float2 vv = *(const float2*)&V[base + i];
        float o0 = 0.f, o1 = 0.f;
        if (u0 >= thr) o0 = vv.x * expf(ord2f(u0) - maxf) * inv;
        if (u1 >= thr) o1 = vv.y * expf(ord2f(u1) - maxf) * inv;
        __nv_bfloat162 h2 = __floats2bfloat162_rn(o0, o1);
        __nv_bfloat162 l2 = __floats2bfloat162_rn(o0 - __bfloat162float(h2.x),
                                                  o1 - __bfloat162float(h2.y));
        *(__nv_bfloat162*)&Hout[base + i] = h2;
        *(__nv_bfloat162*)&Lout[base + i] = l2;
    }
}

// ---------------- launch ----------------
extern "C" void kernel_launch(void* const* d_in, const int* in_sizes, int n_in,
                              void* d_out, int out_size)
{
    const float* x     = (const float*)d_in[0];
    const float* gamma = (const float*)d_in[1];
    const float* beta  = (const float*)d_in[2];
    const float* wq    = (const float*)d_in[3];
    const float* bq    = (const float*)d_in[4];
    const float* wk    = (const float*)d_in[5];
    const float* bk    = (const float*)d_in[6];
    const float* wv    = (const float*)d_in[7];
    const float* bv    = (const float*)d_in[8];
    const float* wf    = (const float*)d_in[9];
    const float* bf    = (const float*)d_in[10];
    float* out = (float*)d_out;

    void *pxn, *pxnh, *pxnl, *pq, *pk, *pv, *pf4h, *pf4l;
    void *pwkh, *pwkl, *pwqvh, *pwqvl, *pwfh, *pwfl, *pbqv;
    cudaGetSymbolAddress(&pxn,  g_xn);
    cudaGetSymbolAddress(&pxnh, g_xnh);
    cudaGetSymbolAddress(&pxnl, g_xnl);
    cudaGetSymbolAddress(&pq,   g_q);
    cudaGetSymbolAddress(&pk,   g_k);
    cudaGetSymbolAddress(&pv,   g_v);
    cudaGetSymbolAddress(&pf4h, g_f4h);
    cudaGetSymbolAddress(&pf4l, g_f4l);
    cudaGetSymbolAddress(&pwkh, g_wkh);
    cudaGetSymbolAddress(&pwkl, g_wkl);
    cudaGetSymbolAddress(&pwqvh, g_wqvh);
    cudaGetSymbolAddress(&pwqvl, g_wqvl);
    cudaGetSymbolAddress(&pwfh, g_wfh);
    cudaGetSymbolAddress(&pwfl, g_wfl);
    cudaGetSymbolAddress(&pbqv, g_bqv);

    cudaFuncSetAttribute(fft_topk_kernel,
                         cudaFuncAttributeMaxDynamicSharedMemorySize, FFT2_SMEM_BYTES);

    // 0. merged prep
    prep_kernel<<<433, 256>>>(wq, wv, wf, wk, bq, bv);

    // 1. GroupNorm (+ bf16 hi/lo planes)
    groupnorm_kernel<<<B_ * NG_, 256>>>(x, gamma, beta);

    // 2. combined q|v projection (M=768, shared B operand)
    dim3 gqv(HW_ / 128, 768 / 128, B_);
    gemm_bf16_kernel<C_, 768, false, false><<<gqv, 256>>>(
        (const __nv_bfloat16*)pwqvh, (const __nv_bfloat16*)pwqvl,
        (const __nv_bfloat16*)pxnh, (const __nv_bfloat16*)pxnl,
        (const float*)pxn, (const float*)pbqv, (float*)pq, (float*)pv);

    // 3. k projection (3x3 implicit GEMM, x4t B-frags)
    dim3 gg(HW_ / 128, C_ / 128, B_);
    gemm_bf16_kernel<C_ * 9, 384, true, false><<<gg, 256>>>(
        (const __nv_bfloat16*)pwkh, (const __nv_bfloat16*)pwkl,
        (const __nv_bfloat16*)pxnh, (const __nv_bfloat16*)pxnl,
        (const float*)pxn, bk, (float*)pk, (float*)pk);

    // 4. fused packed FFT + top-k + softmax + v-mul -> bf16 F4 planes
    fft_topk_kernel<<<B_ * C_, 512, FFT2_SMEM_BYTES>>>(
        (const float*)pq, (const float*)pk, (const float*)pv,
        (__nv_bfloat16*)pf4h, (__nv_bfloat16*)pf4l);

    // 5. final 1x1 conv with xn-multiply epilogue
    gemm_bf16_kernel<C_, 384, false, true><<<gg, 256>>>(
        (const __nv_bfloat16*)pwfh, (const __nv_bfloat16*)pwfl,
        (const __nv_bfloat16*)pf4h, (const __nv_bfloat16*)pf4l,
        (const float*)pxn, bf, out, out);
}